// round 8
// baseline (speedup 1.0000x reference)
#include <cuda_runtime.h>
#include <cuda_bf16.h>
#include <cstdint>

#define FULLMASK 0xffffffffu
#define F_DIM 1024
#define C_DIM 64
#define N_ROWS 65536           // 32*2048
#define PLEN_MAX 1216          // 1024 + 64*3 max pad (each segment padded to mult of 4)
#define NCHUNK_MAX 304

// ---- scratch (device globals; no allocation) ----
__device__ __align__(16) unsigned short g_perm16[F_DIM];      // f -> padded sorted position
__device__ __align__(16) unsigned short g_padpos[C_DIM * 3];  // pad slot positions
__device__ int g_c0[C_DIM];     // segment -> first chunk index
__device__ int g_c1[C_DIM];     // segment -> end chunk index (exclusive)
__device__ int g_nchunk;        // total chunks (256..304)
__device__ int g_npad;          // total pad slots (0..192)
__device__ int g_labIsA;        // 1 if candidate A is the labels buffer
__device__ int g_lab64;         // 1 if labels are 64-bit
__device__ float g_terms[N_ROWS];

// ============================================================
// Detect: disambiguate labels vs mask among the two 65536-elem
// buffers, and label width (int32 vs int64). One block.
//   mask one-hot: ~98% zero words; int64 labels ~51%; int32 ~1.6%.
//   Odd-word OR == 0  <=>  int64 labels.
// ============================================================
__global__ void detect_kernel(const unsigned* __restrict__ A,
                              const unsigned* __restrict__ B) {
    __shared__ int sh[32];
    int t = threadIdx.x, lane = t & 31, wid = t >> 5;

    int zA = 0;
    unsigned oA = 0u, oB = 0u;
    for (int i = t; i < 8192; i += 1024) {
        unsigned wa = A[i], wb = B[i];
        zA += (wa == 0u);
        if (i & 1) { oA |= wa; oB |= wb; }
    }
#pragma unroll
    for (int o = 16; o; o >>= 1) {
        zA += __shfl_xor_sync(FULLMASK, zA, o);
        oA |= __shfl_xor_sync(FULLMASK, oA, o);
        oB |= __shfl_xor_sync(FULLMASK, oB, o);
    }
    if (lane == 0) sh[wid] = zA;
    __syncthreads();
    if (t == 0) { int s = 0; for (int i = 0; i < 32; i++) s += sh[i]; sh[0] = s; }
    __syncthreads();
    int zAt = sh[0];
    __syncthreads();
    if (lane == 0) sh[wid] = (int)(oA != 0u);
    __syncthreads();
    if (t == 0) { int s = 0; for (int i = 0; i < 32; i++) s |= sh[i]; sh[0] = s; }
    __syncthreads();
    int oAt = sh[0];
    __syncthreads();
    if (lane == 0) sh[wid] = (int)(oB != 0u);
    __syncthreads();
    if (t == 0) { int s = 0; for (int i = 0; i < 32; i++) s |= sh[i]; sh[0] = s; }
    __syncthreads();
    int oBt = sh[0];

    if (t == 0) {
        int aIsMask = (zAt > 6000);           // mask ~8064 zero words of 8192
        g_labIsA = aIsMask ? 0 : 1;
        int labOdd = aIsMask ? oBt : oAt;     // odd-word OR of the labels buffer
        g_lab64 = (labOdd == 0) ? 1 : 0;      // high words all zero => int64
    }
}

// ============================================================
// Setup: seg ids, counts, sorted layout padded per segment to a
// multiple of 4 (chunks never straddle segments), perm + pad lists,
// per-segment chunk ranges. One block, 1024 threads.
// ============================================================
__global__ void setup_kernel(const float* __restrict__ candA,
                             const float* __restrict__ candB) {
    __shared__ int sh_seg[F_DIM];
    __shared__ int sh_cnt[C_DIM];
    __shared__ int sh_base[C_DIM];
    __shared__ int sh_padpre[C_DIM];

    const float* mask = g_labIsA ? candB : candA;

    int tid = threadIdx.x;
    if (tid < C_DIM) sh_cnt[tid] = 0;
    __syncthreads();

    int wid = tid >> 5, lane = tid & 31;
    // warp per fine row of mask: find one-hot column via ballot
    for (int f = wid; f < F_DIM; f += 32) {
        float v0 = mask[f * C_DIM + lane];
        float v1 = mask[f * C_DIM + 32 + lane];
        unsigned b0 = __ballot_sync(FULLMASK, v0 > 0.5f);
        unsigned b1 = __ballot_sync(FULLMASK, v1 > 0.5f);
        int c = b0 ? (__ffs(b0) - 1) : (32 + __ffs(b1) - 1);
        if (lane == 0) { sh_seg[f] = c; atomicAdd(&sh_cnt[c], 1); }
    }
    __syncthreads();

    // serial layout: each segment starts 4-aligned, padded to mult of 4
    if (tid == 0) {
        int b = 0, pp = 0;
        for (int s = 0; s < C_DIM; s++) {
            sh_base[s] = b;
            sh_padpre[s] = pp;
            int L = sh_cnt[s];
            int c4 = (L + 3) & ~3;
            pp += c4 - L;
            b  += c4;
        }
        g_nchunk = b >> 2;
        g_npad   = pp;
    }
    __syncthreads();

    // perm positions, chunk ranges, pad slots
    if (tid < C_DIM) {
        int p = sh_base[tid];
        for (int f = 0; f < F_DIM; f++) {
            if (sh_seg[f] == tid) g_perm16[f] = (unsigned short)(p++);
        }
        int L  = sh_cnt[tid];
        int c4 = (L + 3) & ~3;
        g_c0[tid] = sh_base[tid] >> 2;
        g_c1[tid] = (sh_base[tid] + c4) >> 2;
        int pe = sh_padpre[tid];
        for (int k = L; k < c4; k++)
            g_padpos[pe++] = (unsigned short)(sh_base[tid] + k);
    }
}

// ============================================================
// Main: 1 block (256 threads) = 1 row.
//  stage: LDG.128 + perm scatter into padded sorted smem (+ -inf pads)
//  pass1: 1 LDS.128/thread -> chunk max; warp0 segment+row max
//  pass2: 1 LDS.128/thread -> chunk exp-sum; warp0 segment sums + term
// ~8KB smem, 8 blocks/SM.
// ============================================================
__global__ void __launch_bounds__(256, 8)
main_kernel(const float* __restrict__ logits,
            const void* __restrict__ candA, const void* __restrict__ candB) {
    __shared__ __align__(16) float buf[PLEN_MAX];
    __shared__ float cval[NCHUNK_MAX];
    __shared__ float smaxs[C_DIM];
    __shared__ float ssums[C_DIM];
    __shared__ float sh_m;
    __shared__ int   sh_lab;

    const float NEG_INF = __int_as_float(0xff800000);

    int row = blockIdx.x;
    int t = threadIdx.x;

    // prefetch label early (overlaps staging)
    if (t == 0) {
        const void* labp = g_labIsA ? candA : candB;
        sh_lab = g_lab64 ? (int)((const long long*)labp)[row]
                         : ((const int*)labp)[row];
    }

    // stage: coalesced float4 load + uint16-perm scatter into smem
    float4  v = ((const float4*)(logits + (size_t)row * F_DIM))[t];
    ushort4 p = ((const ushort4*)g_perm16)[t];
    int nchunk = g_nchunk;
    int npad   = g_npad;
    buf[p.x] = v.x; buf[p.y] = v.y; buf[p.z] = v.z; buf[p.w] = v.w;
    if (t < npad) buf[g_padpos[t]] = NEG_INF;
    __syncthreads();

    const float4* buf4 = (const float4*)buf;

    // pass 1: per-chunk max (dense LDS.128, conflict-free)
    {
        float4 a = buf4[t];
        cval[t] = fmaxf(fmaxf(a.x, a.y), fmaxf(a.z, a.w));
        if (t + 256 < nchunk) {
            float4 b = buf4[t + 256];
            cval[t + 256] = fmaxf(fmaxf(b.x, b.y), fmaxf(b.z, b.w));
        }
    }
    __syncthreads();

    // warp 0: segment maxes (2 segments per lane) + row max
    if (t < 32) {
        int c00 = g_c0[t],      c01 = g_c1[t];
        int c10 = g_c0[t + 32], c11 = g_c1[t + 32];
        float m0 = NEG_INF, m1 = NEG_INF;
        for (int c = c00; c < c01; c++) m0 = fmaxf(m0, cval[c]);
        for (int c = c10; c < c11; c++) m1 = fmaxf(m1, cval[c]);
        smaxs[t]      = m0;
        smaxs[t + 32] = m1;
        float a = fmaxf(m0, m1);
#pragma unroll
        for (int o = 16; o; o >>= 1) a = fmaxf(a, __shfl_xor_sync(FULLMASK, a, o));
        if (t == 0) sh_m = a;
    }
    __syncthreads();
    float m = sh_m;

    // pass 2: per-chunk sum of exp(v - m); pads give exp(-inf)=0
    {
        float4 a = buf4[t];
        cval[t] = __expf(a.x - m) + __expf(a.y - m)
                + __expf(a.z - m) + __expf(a.w - m);
        if (t + 256 < nchunk) {
            float4 b = buf4[t + 256];
            cval[t + 256] = __expf(b.x - m) + __expf(b.y - m)
                          + __expf(b.z - m) + __expf(b.w - m);
        }
    }
    __syncthreads();

    // warp 0: segment sums, totals, label terms
    if (t < 32) {
        int c00 = g_c0[t],      c01 = g_c1[t];
        int c10 = g_c0[t + 32], c11 = g_c1[t + 32];
        float s0 = 0.f, s1 = 0.f;
        for (int c = c00; c < c01; c++) s0 += cval[c];
        for (int c = c10; c < c11; c++) s1 += cval[c];
        ssums[t]      = s0;
        ssums[t + 32] = s1;
        float e  = s0 + s1;
        float gg = __expf(smaxs[t] - m) + __expf(smaxs[t + 32] - m);
#pragma unroll
        for (int o = 16; o; o >>= 1) {
            e  += __shfl_xor_sync(FULLMASK, e, o);
            gg += __shfl_xor_sync(FULLMASK, gg, o);
        }
        __syncwarp();
        if (t == 0) {
            int lab = sh_lab;
            float cl = smaxs[lab], sl = ssums[lab];
            g_terms[row] = (cl - m - __logf(gg)) + (__logf(sl) - __logf(e));
        }
    }
}

// ============================================================
// Finish: deterministic reduce of 65536 float terms -> scalar
// ============================================================
__global__ void finish_kernel(float* __restrict__ out) {
    __shared__ double sh[1024];
    int t = threadIdx.x;
    double s = 0.0;
    for (int i = t; i < N_ROWS; i += 1024) s += (double)g_terms[i];
    sh[t] = s;
    __syncthreads();
    for (int o = 512; o; o >>= 1) {
        if (t < o) sh[t] += sh[t + o];
        __syncthreads();
    }
    if (t == 0) out[0] = (float)(-0.5 * sh[0] / (double)N_ROWS);
}

extern "C" void kernel_launch(void* const* d_in, const int* in_sizes, int n_in,
                              void* d_out, int out_size) {
    // identify logits by element count; the other two are device-disambiguated
    int li = 0;
    for (int i = 0; i < n_in; i++) if (in_sizes[i] > 1000000) { li = i; break; }
    int o1 = (li == 0) ? 1 : 0;
    int o2 = (li == 2) ? 1 : 2;
    if (o2 == o1) o2 = (o1 == 1) ? 2 : 1;

    const float* logits = (const float*)d_in[li];
    const void*  candA  = d_in[o1];
    const void*  candB  = d_in[o2];
    float*       out    = (float*)d_out;

    detect_kernel<<<1, 1024>>>((const unsigned*)candA, (const unsigned*)candB);
    setup_kernel<<<1, 1024>>>((const float*)candA, (const float*)candB);
    main_kernel<<<N_ROWS, 256>>>(logits, candA, candB);
    finish_kernel<<<1, 1024>>>(out);
}

// round 9
// speedup vs baseline: 1.5015x; 1.5015x over previous
#include <cuda_runtime.h>
#include <cuda_bf16.h>
#include <cstdint>

#define FULLMASK 0xffffffffu
#define F_DIM 1024
#define C_DIM 64
#define N_ROWS 65536           // 32*2048
#define PLEN_MAX 1216          // 1024 + 64*3 max pad (each segment padded to mult of 4)
#define NCHUNK_MAX 304
#define WARPS_PB 8
#define WSTRIDE (PLEN_MAX + NCHUNK_MAX)   // 1520 floats per warp slice

// ---- scratch (device globals; no allocation) ----
__device__ __align__(16) unsigned short g_perm16[F_DIM];      // f -> padded sorted position
__device__ __align__(16) unsigned short g_padpos[C_DIM * 3];  // pad slot positions
__device__ int g_c0[C_DIM];     // segment -> first chunk index
__device__ int g_c1[C_DIM];     // segment -> end chunk index (exclusive)
__device__ int g_nchunk;        // total chunks (256..304)
__device__ int g_npad;          // total pad slots (0..192)
__device__ int g_labIsA;        // 1 if candidate A is the labels buffer
__device__ int g_lab64;         // 1 if labels are 64-bit
__device__ float g_terms[N_ROWS];
__device__ double g_part2[64];

// ============================================================
// Detect: labels vs mask among the two 65536-elem buffers, and
// label width. mask one-hot ~98% zero words; odd-word OR==0 <=> i64.
// ============================================================
__global__ void detect_kernel(const unsigned* __restrict__ A,
                              const unsigned* __restrict__ B) {
    __shared__ int sh[32];
    int t = threadIdx.x, lane = t & 31, wid = t >> 5;

    int zA = 0;
    unsigned oA = 0u, oB = 0u;
    for (int i = t; i < 8192; i += 1024) {
        unsigned wa = A[i], wb = B[i];
        zA += (wa == 0u);
        if (i & 1) { oA |= wa; oB |= wb; }
    }
#pragma unroll
    for (int o = 16; o; o >>= 1) {
        zA += __shfl_xor_sync(FULLMASK, zA, o);
        oA |= __shfl_xor_sync(FULLMASK, oA, o);
        oB |= __shfl_xor_sync(FULLMASK, oB, o);
    }
    if (lane == 0) sh[wid] = zA;
    __syncthreads();
    if (t == 0) { int s = 0; for (int i = 0; i < 32; i++) s += sh[i]; sh[0] = s; }
    __syncthreads();
    int zAt = sh[0];
    __syncthreads();
    if (lane == 0) sh[wid] = (int)(oA != 0u);
    __syncthreads();
    if (t == 0) { int s = 0; for (int i = 0; i < 32; i++) s |= sh[i]; sh[0] = s; }
    __syncthreads();
    int oAt = sh[0];
    __syncthreads();
    if (lane == 0) sh[wid] = (int)(oB != 0u);
    __syncthreads();
    if (t == 0) { int s = 0; for (int i = 0; i < 32; i++) s |= sh[i]; sh[0] = s; }
    __syncthreads();
    int oBt = sh[0];

    if (t == 0) {
        int aIsMask = (zAt > 6000);
        g_labIsA = aIsMask ? 0 : 1;
        int labOdd = aIsMask ? oBt : oAt;
        g_lab64 = (labOdd == 0) ? 1 : 0;
    }
}

// ============================================================
// Setup: seg ids, counts, layout with each segment padded to a
// multiple of 4 (chunks never straddle segments), perm + pad lists,
// per-segment chunk ranges. One block, 1024 threads.
// ============================================================
__global__ void setup_kernel(const float* __restrict__ candA,
                             const float* __restrict__ candB) {
    __shared__ int sh_seg[F_DIM];
    __shared__ int sh_cnt[C_DIM];
    __shared__ int sh_base[C_DIM];
    __shared__ int sh_padpre[C_DIM];

    const float* mask = g_labIsA ? candB : candA;

    int tid = threadIdx.x;
    if (tid < C_DIM) sh_cnt[tid] = 0;
    __syncthreads();

    int wid = tid >> 5, lane = tid & 31;
    for (int f = wid; f < F_DIM; f += 32) {
        float v0 = mask[f * C_DIM + lane];
        float v1 = mask[f * C_DIM + 32 + lane];
        unsigned b0 = __ballot_sync(FULLMASK, v0 > 0.5f);
        unsigned b1 = __ballot_sync(FULLMASK, v1 > 0.5f);
        int c = b0 ? (__ffs(b0) - 1) : (32 + __ffs(b1) - 1);
        if (lane == 0) { sh_seg[f] = c; atomicAdd(&sh_cnt[c], 1); }
    }
    __syncthreads();

    if (tid == 0) {
        int b = 0, pp = 0;
        for (int s = 0; s < C_DIM; s++) {
            sh_base[s] = b;
            sh_padpre[s] = pp;
            int L = sh_cnt[s];
            int c4 = (L + 3) & ~3;
            pp += c4 - L;
            b  += c4;
        }
        g_nchunk = b >> 2;
        g_npad   = pp;
    }
    __syncthreads();

    if (tid < C_DIM) {
        int p = sh_base[tid];
        for (int f = 0; f < F_DIM; f++) {
            if (sh_seg[f] == tid) g_perm16[f] = (unsigned short)(p++);
        }
        int L  = sh_cnt[tid];
        int c4 = (L + 3) & ~3;
        g_c0[tid] = sh_base[tid] >> 2;
        g_c1[tid] = (sh_base[tid] + c4) >> 2;
        int pe = sh_padpre[tid];
        for (int k = L; k < c4; k++)
            g_padpos[pe++] = (unsigned short)(sh_base[tid] + k);
    }
}

// ============================================================
// Main: 1 WARP = 1 row, warp-private smem slice, NO block barriers.
//  8x LDG.128 upfront -> perm scatter -> chunk max (LDS.128) ->
//  per-lane 2-segment maxes -> shuffles -> exp pass -> label-lane
//  segment sum -> term. Only __syncwarp between phases.
// 48.6KB dyn smem -> 4 blocks/SM = 32 independent row pipelines.
// ============================================================
__global__ void __launch_bounds__(256, 4)
main_kernel(const float* __restrict__ logits,
            const void* __restrict__ candA, const void* __restrict__ candB) {
    extern __shared__ __align__(16) float sm[];
    const float NEG_INF = __int_as_float(0xff800000);

    int t = threadIdx.x, wid = t >> 5, lane = t & 31;
    int row = blockIdx.x * WARPS_PB + wid;
    float* buf  = sm + wid * WSTRIDE;
    float* cval = buf + PLEN_MAX;

    // label (lane 0 load + broadcast)
    int lab = 0;
    if (lane == 0) {
        const void* labp = g_labIsA ? candA : candB;
        lab = g_lab64 ? (int)((const long long*)labp)[row]
                      : ((const int*)labp)[row];
    }
    lab = __shfl_sync(FULLMASK, lab, 0);

    int nchunk = g_nchunk, npad = g_npad;

    // stage: 8 independent LDG.128 + L1-hot perm loads, scatter
    const float4*  src4 = (const float4*)(logits + (size_t)row * F_DIM);
    const ushort4* pp4  = (const ushort4*)g_perm16;
    float4  v[8];
    ushort4 pp[8];
#pragma unroll
    for (int k = 0; k < 8; k++) v[k]  = src4[k * 32 + lane];
#pragma unroll
    for (int k = 0; k < 8; k++) pp[k] = pp4[k * 32 + lane];
#pragma unroll
    for (int k = 0; k < 8; k++) {
        buf[pp[k].x] = v[k].x; buf[pp[k].y] = v[k].y;
        buf[pp[k].z] = v[k].z; buf[pp[k].w] = v[k].w;
    }
    for (int i = lane; i < npad; i += 32) buf[g_padpos[i]] = NEG_INF;
    __syncwarp();

    // chunk max pass (dense LDS.128, conflict-free) + row max
    const float4* buf4 = (const float4*)buf;
    float mloc = NEG_INF;
    for (int c = lane; c < nchunk; c += 32) {
        float4 a = buf4[c];
        float cm = fmaxf(fmaxf(a.x, a.y), fmaxf(a.z, a.w));
        cval[c] = cm;
        mloc = fmaxf(mloc, cm);
    }
    __syncwarp();
    float m = mloc;
#pragma unroll
    for (int o = 16; o; o >>= 1) m = fmaxf(m, __shfl_xor_sync(FULLMASK, m, o));

    // per-lane segment maxes (segments lane and lane+32)
    int c0a = g_c0[lane],      c1a = g_c1[lane];
    int c0b = g_c0[lane + 32], c1b = g_c1[lane + 32];
    float m0 = NEG_INF, m1 = NEG_INF;
    for (int c = c0a; c < c1a; c++) m0 = fmaxf(m0, cval[c]);
    for (int c = c0b; c < c1b; c++) m1 = fmaxf(m1, cval[c]);
    float gg = __expf(m0 - m) + __expf(m1 - m);
#pragma unroll
    for (int o = 16; o; o >>= 1) gg += __shfl_xor_sync(FULLMASK, gg, o);

    // exp pass: chunk sums + total
    float eloc = 0.f;
    for (int c = lane; c < nchunk; c += 32) {
        float4 a = buf4[c];
        float cs = __expf(a.x - m) + __expf(a.y - m)
                 + __expf(a.z - m) + __expf(a.w - m);
        cval[c] = cs;
        eloc += cs;
    }
    __syncwarp();
    float e = eloc;
#pragma unroll
    for (int o = 16; o; o >>= 1) e += __shfl_xor_sync(FULLMASK, e, o);

    // label segment: owning lane walks its chunks
    float cl = 0.f, sl = 0.f;
    int owner = lab & 31;
    if (lane == owner) {
        cl = (lab < 32) ? m0 : m1;
        int cc0 = (lab < 32) ? c0a : c0b;
        int cc1 = (lab < 32) ? c1a : c1b;
        for (int c = cc0; c < cc1; c++) sl += cval[c];
    }
    cl = __shfl_sync(FULLMASK, cl, owner);
    sl = __shfl_sync(FULLMASK, sl, owner);

    if (lane == 0)
        g_terms[row] = (cl - m - __logf(gg)) + (__logf(sl) - __logf(e));
}

// ============================================================
// Finish: deterministic two-stage reduce -> scalar
// ============================================================
__global__ void finish1_kernel() {
    __shared__ double sh[256];
    int b = blockIdx.x, t = threadIdx.x;
    double s = 0.0;
    for (int i = t; i < 1024; i += 256) s += (double)g_terms[b * 1024 + i];
    sh[t] = s;
    __syncthreads();
    for (int o = 128; o; o >>= 1) {
        if (t < o) sh[t] += sh[t + o];
        __syncthreads();
    }
    if (t == 0) g_part2[b] = sh[0];
}

__global__ void finish2_kernel(float* __restrict__ out) {
    __shared__ double sh[64];
    int t = threadIdx.x;
    sh[t] = g_part2[t];
    __syncthreads();
    for (int o = 32; o; o >>= 1) {
        if (t < o) sh[t] += sh[t + o];
        __syncthreads();
    }
    if (t == 0) out[0] = (float)(-0.5 * sh[0] / (double)N_ROWS);
}

extern "C" void kernel_launch(void* const* d_in, const int* in_sizes, int n_in,
                              void* d_out, int out_size) {
    // identify logits by element count; the other two are device-disambiguated
    int li = 0;
    for (int i = 0; i < n_in; i++) if (in_sizes[i] > 1000000) { li = i; break; }
    int o1 = (li == 0) ? 1 : 0;
    int o2 = (li == 2) ? 1 : 2;
    if (o2 == o1) o2 = (o1 == 1) ? 2 : 1;

    const float* logits = (const float*)d_in[li];
    const void*  candA  = d_in[o1];
    const void*  candB  = d_in[o2];
    float*       out    = (float*)d_out;

    size_t smem = (size_t)WARPS_PB * WSTRIDE * sizeof(float);   // 48640 B
    cudaFuncSetAttribute(main_kernel, cudaFuncAttributeMaxDynamicSharedMemorySize,
                         (int)smem);

    detect_kernel<<<1, 1024>>>((const unsigned*)candA, (const unsigned*)candB);
    setup_kernel<<<1, 1024>>>((const float*)candA, (const float*)candB);
    main_kernel<<<N_ROWS / WARPS_PB, 256, smem>>>(logits, candA, candB);
    finish1_kernel<<<64, 256>>>();
    finish2_kernel<<<1, 64>>>(out);
}